// round 10
// baseline (speedup 1.0000x reference)
#include <cuda_runtime.h>
#include <math.h>

// GAT_15547781612261 — 6-kernel subgraph-pruned, aggregate-first GAT.
// Round 10 (3rd submit; prior two hit broker-infra failures, not kernel errors).

#define NN 8192
#define EE 32768
#define ET (EE + NN)
#define HH 6
#define DCAP 64
#define M1CAP 8192
#define M2CAP 2048
#define TILE 8

#define C0 1028
#define C1 128
#define C2 256
#define C3 1028
#define W1C 768
#define W2C 1536
#define W3C 6168

// ---------------- device globals ----------------
__device__ int fl0[NN], fl1[NN], fl2[NN], fl3[NN];
__device__ int pos1[NN], pos2[NN];
__device__ int lst0[NN], lst1[M1CAP], lst2[M2CAP];
__device__ int g_cnt[4];                 // 0:M1  1:M2  2:M0
__device__ int nodeB[8];
__device__ int deg1[NN], deg2[NN], deg3[NN];
__device__ int bk1[NN * DCAP], bk2[NN * DCAP], bk3[NN * DCAP];
__device__ float es1a[NN * HH], ed1a[NN * HH];
__device__ float es2a[M1CAP * HH], ed2a[M1CAP * HH];
__device__ float es3a[M2CAP * HH], ed3a[M2CAP * HH];
__device__ float p1s[HH * C0], p1d[HH * C0];
__device__ float p2s[HH * C1], p2d[HH * C1];
__device__ float p3s[HH * C2], p3d[HH * C2];
__device__ float r2s[HH * W3C], r2d[HH * W3C];
__device__ float r3s[HH * 768], r3d[HH * 768];
__device__ float c2s[HH], c2d[HH], c3s[HH], c3d[HH];
__device__ float h1p[(size_t)M1CAP * HH * C1];   // per-head partials (b1 folded into h=0)
__device__ float h2p[(size_t)M2CAP * HH * C2];   // b2 folded into h=0

// ================= kA: zero + p-vectors (warp per dot) =================
__global__ void kA_init(const float* __restrict__ W1, const float* __restrict__ as1, const float* __restrict__ ad1,
                        const float* __restrict__ W2, const float* __restrict__ as2, const float* __restrict__ ad2,
                        const float* __restrict__ W3, const float* __restrict__ as3, const float* __restrict__ ad3,
                        float* __restrict__ out) {
    int tid = blockIdx.x * blockDim.x + threadIdx.x;
    int stride = gridDim.x * blockDim.x;
    for (int i = tid; i < NN; i += stride) {
        fl0[i] = 0; fl1[i] = 0; fl2[i] = 0; fl3[i] = 0;
        deg1[i] = 0; deg2[i] = 0; deg3[i] = 0;
    }
    for (int i = tid; i < M1CAP * HH; i += stride) { es2a[i] = 0.f; ed2a[i] = 0.f; }
    for (int i = tid; i < M2CAP * HH; i += stride) { es3a[i] = 0.f; ed3a[i] = 0.f; }
    for (int i = tid; i < 8 * C3; i += stride) out[i] = 0.f;
    if (tid < 4) g_cnt[tid] = 0;

    int w = tid >> 5, lane = tid & 31, nw = stride >> 5;
    for (int it = w; it < HH * C0; it += nw) {
        int h = it % HH, k = it / HH;
        const float* wr = W1 + (size_t)k * W1C + h * C1;
        const float* va = as1 + h * C1;
        const float* vd = ad1 + h * C1;
        float ss = 0.f, sd = 0.f;
        #pragma unroll
        for (int j = 0; j < C1 / 32; j++) {
            int c = lane + j * 32;
            float wv = wr[c];
            ss += wv * va[c]; sd += wv * vd[c];
        }
        #pragma unroll
        for (int o = 16; o > 0; o >>= 1) { ss += __shfl_down_sync(~0u, ss, o); sd += __shfl_down_sync(~0u, sd, o); }
        if (lane == 0) { p1s[h * C0 + k] = ss; p1d[h * C0 + k] = sd; }
    }
    for (int it = w; it < HH * C1; it += nw) {
        int h = it % HH, k = it / HH;
        const float* wr = W2 + (size_t)k * W2C + h * C2;
        const float* va = as2 + h * C2;
        const float* vd = ad2 + h * C2;
        float ss = 0.f, sd = 0.f;
        #pragma unroll
        for (int j = 0; j < C2 / 32; j++) {
            int c = lane + j * 32;
            float wv = wr[c];
            ss += wv * va[c]; sd += wv * vd[c];
        }
        #pragma unroll
        for (int o = 16; o > 0; o >>= 1) { ss += __shfl_down_sync(~0u, ss, o); sd += __shfl_down_sync(~0u, sd, o); }
        if (lane == 0) { p2s[h * C1 + k] = ss; p2d[h * C1 + k] = sd; }
    }
    for (int it = w; it < HH * C2; it += nw) {
        int h = it % HH, k = it / HH;
        const float* wr = W3 + (size_t)k * W3C + h * C3;
        const float* va = as3 + h * C3;
        const float* vd = ad3 + h * C3;
        float ss = 0.f, sd = 0.f;
        for (int j = 0; j < 33; j++) {
            int c = lane + j * 32;
            if (c < C3) { float wv = wr[c]; ss += wv * va[c]; sd += wv * vd[c]; }
        }
        #pragma unroll
        for (int o = 16; o > 0; o >>= 1) { ss += __shfl_down_sync(~0u, ss, o); sd += __shfl_down_sync(~0u, sd, o); }
        if (lane == 0) { p3s[h * C2 + k] = ss; p3d[h * C2 + k] = sd; }
    }
}

// ================= kB: single-block BFS + compact + buckets =================
__global__ __launch_bounds__(1024) void kB_graph(const int* __restrict__ ei,
                                                 const int* __restrict__ ptr) {
    int t = threadIdx.x;
    if (t < 8) {
        int node = ptr[t + 1] - 1;
        nodeB[t] = node;
        fl3[node] = 1; fl2[node] = 1; fl1[node] = 1; fl0[node] = 1;
    }
    __syncthreads();
    for (int e = t; e < EE; e += 1024) {
        int d = ei[EE + e];
        if (fl3[d]) { int s = ei[e]; fl2[s] = 1; fl1[s] = 1; fl0[s] = 1; }
    }
    __syncthreads();
    for (int e = t; e < EE; e += 1024) {
        int d = ei[EE + e];
        if (fl2[d]) { int s = ei[e]; fl1[s] = 1; fl0[s] = 1; }
    }
    __syncthreads();
    for (int e = t; e < EE; e += 1024) {
        int d = ei[EE + e];
        if (fl1[d]) fl0[ei[e]] = 1;
    }
    __syncthreads();
    for (int i = t; i < NN; i += 1024) {
        if (fl0[i]) { int j = atomicAdd(&g_cnt[2], 1); lst0[j] = i; }
        if (fl1[i]) { int j = atomicAdd(&g_cnt[0], 1); if (j < M1CAP) { lst1[j] = i; pos1[i] = j; } }
        if (fl2[i]) { int j = atomicAdd(&g_cnt[1], 1); if (j < M2CAP) { lst2[j] = i; pos2[i] = j; } }
    }
    __syncthreads();
    for (int e = t; e < ET; e += 1024) {
        int s, d;
        if (e < EE) { s = ei[e]; d = ei[EE + e]; }
        else        { s = e - EE; d = e - EE; }
        if (fl1[d]) { int j = atomicAdd(&deg1[d], 1); if (j < DCAP) bk1[d * DCAP + j] = s; }
        if (fl2[d]) { int j = atomicAdd(&deg2[d], 1); if (j < DCAP) bk2[d * DCAP + j] = s; }
        if (fl3[d]) { int j = atomicAdd(&deg3[d], 1); if (j < DCAP) bk3[d * DCAP + j] = s; }
    }
}

// ================= kC: r2/r3 + c2/c3 + es1/ed1 (V0 only) =================
__global__ void kC_prep(const float* __restrict__ x,
                        const float* __restrict__ W1, const float* __restrict__ W2,
                        const float* __restrict__ b1, const float* __restrict__ b2) {
    int tid = blockIdx.x * blockDim.x + threadIdx.x;
    int stride = gridDim.x * blockDim.x;
    int w = tid >> 5, lane = tid & 31, nw = stride >> 5;

    // r2[h2, K=(head,k)] = sum_kc W1[k, head*128+kc] * p2[h2, kc]
    for (int it = w; it < HH * W3C; it += nw) {
        int h2 = it % HH, K = it / HH;
        int head = K / C0, k = K - head * C0;
        const float* wr = W1 + (size_t)k * W1C + head * C1;
        const float* ps = p2s + h2 * C1;
        const float* pd = p2d + h2 * C1;
        float ss = 0.f, sd = 0.f;
        #pragma unroll
        for (int j = 0; j < C1 / 32; j++) {
            int c = lane + j * 32;
            float wv = wr[c];
            ss += wv * ps[c]; sd += wv * pd[c];
        }
        #pragma unroll
        for (int o = 16; o > 0; o >>= 1) { ss += __shfl_down_sync(~0u, ss, o); sd += __shfl_down_sync(~0u, sd, o); }
        if (lane == 0) { r2s[h2 * W3C + K] = ss; r2d[h2 * W3C + K] = sd; }
    }
    // r3[h3, K=(head,k)] over 768
    for (int it = w; it < HH * 768; it += nw) {
        int h3 = it % HH, K = it / HH;
        int head = K / C1, k = K - head * C1;
        const float* wr = W2 + (size_t)k * W2C + head * C2;
        const float* ps = p3s + h3 * C2;
        const float* pd = p3d + h3 * C2;
        float ss = 0.f, sd = 0.f;
        #pragma unroll
        for (int j = 0; j < C2 / 32; j++) {
            int c = lane + j * 32;
            float wv = wr[c];
            ss += wv * ps[c]; sd += wv * pd[c];
        }
        #pragma unroll
        for (int o = 16; o > 0; o >>= 1) { ss += __shfl_down_sync(~0u, ss, o); sd += __shfl_down_sync(~0u, sd, o); }
        if (lane == 0) { r3s[h3 * 768 + K] = ss; r3d[h3 * 768 + K] = sd; }
    }
    // c2[h2] = b1·p2[h2], c3[h3] = b2·p3[h3]
    for (int it = w; it < 2 * HH; it += nw) {
        int h = it % HH;
        float ss = 0.f, sd = 0.f;
        if (it < HH) {
            #pragma unroll
            for (int j = 0; j < C1 / 32; j++) {
                int c = lane + j * 32;
                float bb = b1[c];
                ss += bb * p2s[h * C1 + c]; sd += bb * p2d[h * C1 + c];
            }
        } else {
            #pragma unroll
            for (int j = 0; j < C2 / 32; j++) {
                int c = lane + j * 32;
                float bb = b2[c];
                ss += bb * p3s[h * C2 + c]; sd += bb * p3d[h * C2 + c];
            }
        }
        #pragma unroll
        for (int o = 16; o > 0; o >>= 1) { ss += __shfl_down_sync(~0u, ss, o); sd += __shfl_down_sync(~0u, sd, o); }
        if (lane == 0) {
            if (it < HH) { c2s[h] = ss; c2d[h] = sd; }
            else         { c3s[h] = ss; c3d[h] = sd; }
        }
    }
    // es1/ed1 only for V0 nodes
    int M0 = g_cnt[2];
    for (int it = w; it < M0 * HH; it += nw) {
        int i = lst0[it / HH], h = it % HH;
        const float* xr = x + (size_t)i * C0;
        const float* ps = p1s + h * C0;
        const float* pd = p1d + h * C0;
        float ss = 0.f, sd = 0.f;
        for (int j = 0; j < 33; j++) {
            int k = lane + j * 32;
            if (k < C0) { float xv = xr[k]; ss += xv * ps[k]; sd += xv * pd[k]; }
        }
        #pragma unroll
        for (int o = 16; o > 0; o >>= 1) { ss += __shfl_down_sync(~0u, ss, o); sd += __shfl_down_sync(~0u, sd, o); }
        if (lane == 0) { es1a[i * HH + h] = ss; ed1a[i * HH + h] = sd; }
    }
}

// ================= kD: layer-1 fused, 8 dst-nodes per block =================
__global__ __launch_bounds__(256) void kD_layer1(const float* __restrict__ x,
                                                 const float* __restrict__ W1,
                                                 const float* __restrict__ b1) {
    __shared__ float sagg[TILE][C0];     // 32.9 KB
    __shared__ float sE[TILE][DCAP];
    __shared__ int   sS[TILE][DCAP];
    __shared__ float sInv[TILE];

    int M1 = g_cnt[0]; if (M1 > M1CAP) M1 = M1CAP;
    int nTiles = (M1 + TILE - 1) / TILE;
    int t = threadIdx.x;
    int w = t >> 5, lane = t & 31;

    for (int bi = blockIdx.x; bi < nTiles * HH; bi += gridDim.x) {
        int h = bi % HH, tile = bi / HH;
        int nValid = M1 - tile * TILE; if (nValid > TILE) nValid = TILE;

        if (w < TILE && w < nValid) {
            int node = lst1[tile * TILE + w];
            int dg = deg1[node]; if (dg > DCAP) dg = DCAP;
            float edv = ed1a[node * HH + h];
            float z = 0.f;
            for (int j = lane; j < dg; j += 32) {
                int s = bk1[node * DCAP + j];
                sS[w][j] = s;
                float v = es1a[s * HH + h] + edv;
                v = (v >= 0.f) ? v : 0.2f * v;
                float e = __expf(v);
                sE[w][j] = e;
                z += e;
            }
            #pragma unroll
            for (int o = 16; o > 0; o >>= 1) z += __shfl_down_sync(~0u, z, o);
            if (lane == 0) sInv[w] = 1.0f / (6.0f * z);
        }
        __syncthreads();

        for (int item = t; item < nValid * C0; item += 256) {
            int n = item / C0, k = item - n * C0;
            int node = lst1[tile * TILE + n];
            int dg = deg1[node]; if (dg > DCAP) dg = DCAP;
            float acc = 0.f;
            for (int j = 0; j < dg; j++)
                acc += sE[n][j] * x[(size_t)sS[n][j] * C0 + k];
            sagg[n][k] = acc * sInv[n];
        }
        for (int item = t + nValid * C0; item < TILE * C0; item += 256)
            sagg[item / C0][item % C0] = 0.f;
        __syncthreads();

        {
            int c = t & 127, grp = t >> 7;
            int nb = grp * 4;
            const float* wcol = W1 + h * C1 + c;
            float a0 = 0.f, a1 = 0.f, a2 = 0.f, a3 = 0.f;
            for (int k = 0; k < C0; k++) {
                float wv = wcol[(size_t)k * W1C];
                a0 += sagg[nb + 0][k] * wv;
                a1 += sagg[nb + 1][k] * wv;
                a2 += sagg[nb + 2][k] * wv;
                a3 += sagg[nb + 3][k] * wv;
            }
            float bb = (h == 0) ? b1[c] : 0.f;
            if (nb + 0 < nValid) h1p[((size_t)(tile * TILE + nb + 0) * HH + h) * C1 + c] = a0 + bb;
            if (nb + 1 < nValid) h1p[((size_t)(tile * TILE + nb + 1) * HH + h) * C1 + c] = a1 + bb;
            if (nb + 2 < nValid) h1p[((size_t)(tile * TILE + nb + 2) * HH + h) * C1 + c] = a2 + bb;
            if (nb + 3 < nValid) h1p[((size_t)(tile * TILE + nb + 3) * HH + h) * C1 + c] = a3 + bb;
        }

        for (int item = w; item < nValid * HH; item += 8) {
            int n = item / HH, h2 = item % HH;
            const float* rs = r2s + h2 * W3C + h * C0;
            const float* rd = r2d + h2 * W3C + h * C0;
            float a = 0.f, b = 0.f;
            for (int k = lane; k < C0; k += 32) {
                float sv = sagg[n][k];
                a += sv * rs[k]; b += sv * rd[k];
            }
            #pragma unroll
            for (int o = 16; o > 0; o >>= 1) { a += __shfl_down_sync(~0u, a, o); b += __shfl_down_sync(~0u, b, o); }
            if (lane == 0) {
                if (h == 0) { a += c2s[h2]; b += c2d[h2]; }
                int i1 = tile * TILE + n;
                atomicAdd(&es2a[i1 * HH + h2], a);
                atomicAdd(&ed2a[i1 * HH + h2], b);
            }
        }
        __syncthreads();
    }
}

// ================= kE: layer-2 fused (block per (i2, h)) =================
__global__ void kE_layer2(const float* __restrict__ W2, const float* __restrict__ b2) {
    __shared__ float sagg[C1];
    __shared__ float sE[DCAP];
    __shared__ int   sS[DCAP];
    __shared__ float sInv;

    int M2 = g_cnt[1]; if (M2 > M2CAP) M2 = M2CAP;
    int t = threadIdx.x;
    for (int bi = blockIdx.x; bi < M2 * HH; bi += gridDim.x) {
        int i2 = bi / HH, h = bi % HH;
        int node = lst2[i2];
        int dg = deg2[node]; if (dg > DCAP) dg = DCAP;
        int dIdx = pos1[node];
        if (t < dg) {
            int s = bk2[node * DCAP + t];
            int sIdx = pos1[s];
            sS[t] = sIdx;
            float v = es2a[sIdx * HH + h] + ed2a[dIdx * HH + h];
            v = (v >= 0.f) ? v : 0.2f * v;
            sE[t] = __expf(v);
        }
        __syncthreads();
        if (t == 0) {
            float z = 0.f;
            for (int j = 0; j < dg; j++) z += sE[j];
            sInv = 1.0f / (6.0f * z);
        }
        __syncthreads();
        float inv = sInv;
        if (t < C1) {
            int k = t;
            float acc = 0.f;
            for (int j = 0; j < dg; j++) {
                const float* hp = h1p + (size_t)sS[j] * HH * C1 + k;
                float hs = hp[0] + hp[C1] + hp[2 * C1] + hp[3 * C1] + hp[4 * C1] + hp[5 * C1];
                acc += sE[j] * hs;
            }
            sagg[k] = acc * inv;
        }
        __syncthreads();
        {
            int c = t;
            const float* wcol = W2 + h * C2 + c;
            float acc = 0.f;
            #pragma unroll 4
            for (int k = 0; k < C1; k++)
                acc += sagg[k] * wcol[(size_t)k * W2C];
            if (h == 0) acc += b2[c];
            h2p[((size_t)i2 * HH + h) * C2 + c] = acc;
        }
        for (int h3 = 0; h3 < HH; h3++) {
            const float* rs = r3s + h3 * 768 + h * C1;
            const float* rd = r3d + h3 * 768 + h * C1;
            float a = 0.f, b = 0.f;
            if (t < C1) {
                float sv = sagg[t];
                a = sv * rs[t]; b = sv * rd[t];
            }
            if (h == 0 && t == 0) { a += c3s[h3]; b += c3d[h3]; }
            #pragma unroll
            for (int o = 16; o > 0; o >>= 1) { a += __shfl_down_sync(~0u, a, o); b += __shfl_down_sync(~0u, b, o); }
            if ((t & 31) == 0 && t < C1) {
                atomicAdd(&es3a[i2 * HH + h3], a);
                atomicAdd(&ed3a[i2 * HH + h3], b);
            }
        }
        __syncthreads();
    }
}

// ================= kF: layer-3 fused + residual (block per (b, h)) =================
__global__ void kF_layer3(const float* __restrict__ x, const float* __restrict__ W3,
                          const float* __restrict__ b3, float* __restrict__ out) {
    __shared__ float sagg[C2];
    __shared__ float sE[DCAP];
    __shared__ int   sS[DCAP];
    __shared__ float sInv;

    int t = threadIdx.x;
    for (int bi = blockIdx.x; bi < 8 * HH; bi += gridDim.x) {
        int b = bi / HH, h = bi % HH;
        int node = nodeB[b];
        int dg = deg3[node]; if (dg > DCAP) dg = DCAP;
        int dIdx = pos2[node];
        if (t < dg) {
            int s = bk3[node * DCAP + t];
            int sIdx = pos2[s];
            sS[t] = sIdx;
            float v = es3a[sIdx * HH + h] + ed3a[dIdx * HH + h];
            v = (v >= 0.f) ? v : 0.f;           // slope 0
            sE[t] = __expf(v);
        }
        __syncthreads();
        if (t == 0) {
            float z = 0.f;
            for (int j = 0; j < dg; j++) z += sE[j];
            sInv = 1.0f / (6.0f * z);
        }
        __syncthreads();
        float inv = sInv;
        if (t < C2) {
            int k = t;
            float acc = 0.f;
            for (int j = 0; j < dg; j++) {
                const float* hp = h2p + (size_t)sS[j] * HH * C2 + k;
                float hs = hp[0] + hp[C2] + hp[2 * C2] + hp[3 * C2] + hp[4 * C2] + hp[5 * C2];
                acc += sE[j] * hs;
            }
            sagg[k] = acc * inv;
        }
        __syncthreads();
        for (int c = t; c < C3; c += 256) {
            const float* wcol = W3 + h * C3 + c;
            float acc = 0.f;
            #pragma unroll 4
            for (int k = 0; k < C2; k++)
                acc += sagg[k] * wcol[(size_t)k * W3C];
            if (h == 0) acc += b3[c] + x[(size_t)node * C0 + c];
            atomicAdd(&out[b * C3 + c], acc);
        }
        __syncthreads();
    }
}

// ---------------- launch ----------------
extern "C" void kernel_launch(void* const* d_in, const int* in_sizes, int n_in,
                              void* d_out, int out_size) {
    const float* x   = (const float*)d_in[0];
    const int*   ei  = (const int*)d_in[1];
    const int*   ptr = (const int*)d_in[2];
    const float* W1  = (const float*)d_in[3];
    const float* as1 = (const float*)d_in[4];
    const float* ad1 = (const float*)d_in[5];
    const float* b1  = (const float*)d_in[6];
    const float* W2  = (const float*)d_in[7];
    const float* as2 = (const float*)d_in[8];
    const float* ad2 = (const float*)d_in[9];
    const float* b2  = (const float*)d_in[10];
    const float* W3  = (const float*)d_in[11];
    const float* as3 = (const float*)d_in[12];
    const float* ad3 = (const float*)d_in[13];
    const float* b3  = (const float*)d_in[14];
    float* out = (float*)d_out;

    kA_init<<<512, 256>>>(W1, as1, ad1, W2, as2, ad2, W3, as3, ad3, out);
    kB_graph<<<1, 1024>>>(ei, ptr);
    kC_prep<<<512, 256>>>(x, W1, W2, b1, b2);
    kD_layer1<<<256, 256>>>(x, W1, b1);
    kE_layer2<<<512, 256>>>(W2, b2);
    kF_layer3<<<48, 256>>>(x, W3, b3, out);
}